// round 1
// baseline (speedup 1.0000x reference)
#include <cuda_runtime.h>
#include <math.h>

#define T_SEQ   2048
#define D_MODEL 1024
#define NH      16
#define DH      64
#define CHUNK   128
#define NCHUNK  (T_SEQ / CHUNK)   // 16

// ---------------- scratch (static __device__ arrays; no allocation) ----------
__device__ __align__(256) float g_q  [T_SEQ * D_MODEL];  // softplus(q), later qf
__device__ __align__(256) float g_g  [T_SEQ * D_MODEL];  // sigmoid(gate)
__device__ __align__(256) float g_kf [T_SEQ * D_MODEL];  // softplus(k)
__device__ __align__(256) float g_v  [T_SEQ * D_MODEL];
__device__ __align__(256) float g_at [T_SEQ * D_MODEL];  // attention output pre-Wo
__device__ __align__(256) float g_Sc  [NH * NCHUNK * DH * DH]; // per-chunk local state
__device__ __align__(256) float g_Spre[NH * NCHUNK * DH * DH]; // exclusive prefix state
__device__ __align__(256) float g_zc  [NH * NCHUNK * DH];
__device__ __align__(256) float g_zpre[NH * NCHUNK * DH];

__device__ __forceinline__ float softplus_f(float x) {
    return (x > 20.f) ? x : log1pf(expf(x));
}

// ---------------- fp32 tiled GEMM: C[M,N] = A[M,K] * B[N,K]^T (+epilogue) ----
// MODE 0: identity, MODE 1: softplus, MODE 2: sigmoid(x + bias[col])
template <int MODE>
__global__ __launch_bounds__(256) void gemm_nt_kernel(
    const float* __restrict__ A, const float* __restrict__ B,
    const float* __restrict__ bias, float* __restrict__ C,
    int M, int N, int K)
{
    __shared__ float As[16][132];
    __shared__ float Bs[16][132];
    const int tid = threadIdx.x;
    const int m0 = blockIdx.y * 128, n0 = blockIdx.x * 128;
    const int tx = tid & 15, ty = tid >> 4;
    float acc[8][8] = {};
    const float* Aptr = A + (size_t)m0 * K;
    const float* Bptr = B + (size_t)n0 * K;

    for (int kt = 0; kt < K; kt += 16) {
        #pragma unroll
        for (int r = 0; r < 2; r++) {
            int l   = tid + r * 256;
            int row = l >> 2;
            int c4  = (l & 3) << 2;
            float4 va = *(const float4*)&Aptr[(size_t)row * K + kt + c4];
            As[c4 + 0][row] = va.x; As[c4 + 1][row] = va.y;
            As[c4 + 2][row] = va.z; As[c4 + 3][row] = va.w;
            float4 vb = *(const float4*)&Bptr[(size_t)row * K + kt + c4];
            Bs[c4 + 0][row] = vb.x; Bs[c4 + 1][row] = vb.y;
            Bs[c4 + 2][row] = vb.z; Bs[c4 + 3][row] = vb.w;
        }
        __syncthreads();
        #pragma unroll
        for (int k = 0; k < 16; k++) {
            float ar[8], br[8];
            *(float4*)&ar[0] = *(float4*)&As[k][ty * 8];
            *(float4*)&ar[4] = *(float4*)&As[k][ty * 8 + 4];
            *(float4*)&br[0] = *(float4*)&Bs[k][tx * 8];
            *(float4*)&br[4] = *(float4*)&Bs[k][tx * 8 + 4];
            #pragma unroll
            for (int i = 0; i < 8; i++)
                #pragma unroll
                for (int j = 0; j < 8; j++)
                    acc[i][j] = fmaf(ar[i], br[j], acc[i][j]);
        }
        __syncthreads();
    }

    #pragma unroll
    for (int i = 0; i < 8; i++) {
        int row = m0 + ty * 8 + i;
        #pragma unroll
        for (int j = 0; j < 8; j++) {
            int col = n0 + tx * 8 + j;
            float vv = acc[i][j];
            if (MODE == 2) vv = 1.f / (1.f + expf(-(vv + bias[col])));
            if (MODE == 1) vv = softplus_f(vv);
            C[(size_t)row * N + col] = vv;
        }
    }
}

// qf = softplus(q) * (sigmoid(gate) + 1e-6)
__global__ void combine_qg_kernel() {
    int i = blockIdx.x * 256 + threadIdx.x;
    g_q[i] = g_q[i] * (g_g[i] + 1e-6f);
}

// ------------- per-(head,chunk) local state S_c = Kf^T V, z_c = sum kf ------
__global__ __launch_bounds__(256) void chunk_state_kernel() {
    extern __shared__ float sm[];
    float* Kc = sm;               // [128][64]
    float* Vc = sm + CHUNK * DH;  // [128][64]
    const int head = blockIdx.x >> 4, chunk = blockIdx.x & 15;
    const int t0 = chunk * CHUNK, col0 = head * DH;
    const int tid = threadIdx.x;

    for (int i = tid; i < CHUNK * DH / 4; i += 256) {
        int t = i >> 4, c4 = (i & 15) << 2;
        *(float4*)&Kc[t * DH + c4] = *(const float4*)&g_kf[(size_t)(t0 + t) * D_MODEL + col0 + c4];
        *(float4*)&Vc[t * DH + c4] = *(const float4*)&g_v [(size_t)(t0 + t) * D_MODEL + col0 + c4];
    }
    __syncthreads();

    const int d = tid >> 2, e0 = (tid & 3) << 4;
    float acc[16] = {};
    float z = 0.f;
    for (int t = 0; t < CHUNK; t++) {
        float kv = Kc[t * DH + d];
        z += kv;
        #pragma unroll
        for (int jj = 0; jj < 4; jj++) {
            float4 vv = *(float4*)&Vc[t * DH + e0 + jj * 4];
            acc[jj * 4 + 0] = fmaf(kv, vv.x, acc[jj * 4 + 0]);
            acc[jj * 4 + 1] = fmaf(kv, vv.y, acc[jj * 4 + 1]);
            acc[jj * 4 + 2] = fmaf(kv, vv.z, acc[jj * 4 + 2]);
            acc[jj * 4 + 3] = fmaf(kv, vv.w, acc[jj * 4 + 3]);
        }
    }
    size_t base = (size_t)blockIdx.x * (DH * DH);
    #pragma unroll
    for (int j = 0; j < 16; j++) g_Sc[base + d * DH + e0 + j] = acc[j];
    if ((tid & 3) == 0) g_zc[blockIdx.x * DH + d] = z;
}

// ------------- sequential prefix over the 16 chunks (per head) --------------
__global__ __launch_bounds__(256) void prefix_kernel(float* __restrict__ out) {
    const int head = blockIdx.x, tid = threadIdx.x;
    float acc[16] = {};
    for (int c = 0; c < NCHUNK; c++) {
        size_t base = ((size_t)head * NCHUNK + c) * (DH * DH);
        #pragma unroll
        for (int k = 0; k < 16; k++) {
            g_Spre[base + tid + k * 256] = acc[k];
            acc[k] += g_Sc[base + tid + k * 256];
        }
    }
    float* kv_out = out + (size_t)T_SEQ * D_MODEL;
    #pragma unroll
    for (int k = 0; k < 16; k++)
        kv_out[(size_t)head * DH * DH + tid + k * 256] = acc[k];

    if (tid < DH) {
        float z = 0.f;
        for (int c = 0; c < NCHUNK; c++) {
            int base = (head * NCHUNK + c) * DH;
            g_zpre[base + tid] = z;
            z += g_zc[base + tid];
        }
        float* z_out = out + (size_t)T_SEQ * D_MODEL + NH * DH * DH;
        z_out[head * DH + tid] = z;
    }
}

// ------------- per-(head,chunk) output: causal intra + inter via S_prefix ---
#define QT_STRIDE 132
#define AS_STRIDE 132
#define CO_SMEM_FLOATS (DH*QT_STRIDE*2 + CHUNK*DH + DH*DH + CHUNK*AS_STRIDE + DH + CHUNK)

__global__ __launch_bounds__(256) void chunk_out_kernel() {
    extern __shared__ float sm[];
    float* Qt  = sm;                          // [64][132] k-major
    float* Kt  = Qt + DH * QT_STRIDE;         // [64][132] k-major
    float* Vs  = Kt + DH * QT_STRIDE;         // [128][64]
    float* Ss  = Vs + CHUNK * DH;             // [64][64]
    float* As  = Ss + DH * DH;                // [128][132]
    float* zs  = As + CHUNK * AS_STRIDE;      // [64]
    float* den = zs + DH;                     // [128]
    const int head = blockIdx.x >> 4, chunk = blockIdx.x & 15;
    const int t0 = chunk * CHUNK, col0 = head * DH;
    const int tid = threadIdx.x;

    for (int i = tid; i < CHUNK * DH / 4; i += 256) {
        int t = i >> 4, c4 = (i & 15) << 2;
        float4 q4 = *(const float4*)&g_q [(size_t)(t0 + t) * D_MODEL + col0 + c4];
        Qt[(c4 + 0) * QT_STRIDE + t] = q4.x; Qt[(c4 + 1) * QT_STRIDE + t] = q4.y;
        Qt[(c4 + 2) * QT_STRIDE + t] = q4.z; Qt[(c4 + 3) * QT_STRIDE + t] = q4.w;
        float4 k4 = *(const float4*)&g_kf[(size_t)(t0 + t) * D_MODEL + col0 + c4];
        Kt[(c4 + 0) * QT_STRIDE + t] = k4.x; Kt[(c4 + 1) * QT_STRIDE + t] = k4.y;
        Kt[(c4 + 2) * QT_STRIDE + t] = k4.z; Kt[(c4 + 3) * QT_STRIDE + t] = k4.w;
        *(float4*)&Vs[t * DH + c4] = *(const float4*)&g_v[(size_t)(t0 + t) * D_MODEL + col0 + c4];
    }
    {
        size_t base = ((size_t)head * NCHUNK + chunk) * (DH * DH);
        for (int i = tid; i < DH * DH / 4; i += 256)
            *(float4*)&Ss[i * 4] = *(const float4*)&g_Spre[base + i * 4];
    }
    if (tid < DH)    zs[tid]  = g_zpre[(head * NCHUNK + chunk) * DH + tid];
    if (tid < CHUNK) den[tid] = 0.f;
    __syncthreads();

    // Phase A: A[t][s] = qf_t . kf_s, masked s<=t; accumulate row sums into den
    {
        const int tx = tid & 15, ty = tid >> 4;
        float a[8][8] = {};
        for (int k = 0; k < DH; k++) {
            float qr[8], kr[8];
            *(float4*)&qr[0] = *(float4*)&Qt[k * QT_STRIDE + ty * 8];
            *(float4*)&qr[4] = *(float4*)&Qt[k * QT_STRIDE + ty * 8 + 4];
            *(float4*)&kr[0] = *(float4*)&Kt[k * QT_STRIDE + tx * 8];
            *(float4*)&kr[4] = *(float4*)&Kt[k * QT_STRIDE + tx * 8 + 4];
            #pragma unroll
            for (int i = 0; i < 8; i++)
                #pragma unroll
                for (int j = 0; j < 8; j++)
                    a[i][j] = fmaf(qr[i], kr[j], a[i][j]);
        }
        #pragma unroll
        for (int i = 0; i < 8; i++) {
            int t = ty * 8 + i;
            float rs = 0.f;
            #pragma unroll
            for (int j = 0; j < 8; j++) {
                int s = tx * 8 + j;
                float vv = (s <= t) ? a[i][j] : 0.f;
                As[t * AS_STRIDE + s] = vv;
                rs += vv;
            }
            atomicAdd(&den[t], rs);
        }
    }
    __syncthreads();
    if (tid < CHUNK) {
        float dz = 0.f;
        #pragma unroll 8
        for (int d = 0; d < DH; d++) dz += Qt[d * QT_STRIDE + tid] * zs[d];
        den[tid] += dz + 1e-6f;
    }
    __syncthreads();

    // Phase B: out[t][e] = (qf_t @ Spre + A[t,:] @ V) / den[t]
    {
        const int t = tid & 127;
        const int e0 = (tid >> 7) * 32;
        float acc[32] = {};
        for (int d = 0; d < DH; d++) {
            float qv = Qt[d * QT_STRIDE + t];
            #pragma unroll
            for (int jj = 0; jj < 8; jj++) {
                float4 sv = *(float4*)&Ss[d * DH + e0 + jj * 4];
                acc[jj * 4 + 0] = fmaf(qv, sv.x, acc[jj * 4 + 0]);
                acc[jj * 4 + 1] = fmaf(qv, sv.y, acc[jj * 4 + 1]);
                acc[jj * 4 + 2] = fmaf(qv, sv.z, acc[jj * 4 + 2]);
                acc[jj * 4 + 3] = fmaf(qv, sv.w, acc[jj * 4 + 3]);
            }
        }
        for (int s = 0; s < CHUNK; s++) {
            float av = As[t * AS_STRIDE + s];
            #pragma unroll
            for (int jj = 0; jj < 8; jj++) {
                float4 vv = *(float4*)&Vs[s * DH + e0 + jj * 4];
                acc[jj * 4 + 0] = fmaf(av, vv.x, acc[jj * 4 + 0]);
                acc[jj * 4 + 1] = fmaf(av, vv.y, acc[jj * 4 + 1]);
                acc[jj * 4 + 2] = fmaf(av, vv.z, acc[jj * 4 + 2]);
                acc[jj * 4 + 3] = fmaf(av, vv.w, acc[jj * 4 + 3]);
            }
        }
        float dinv = 1.f / den[t];
        #pragma unroll
        for (int jj = 0; jj < 8; jj++) {
            float4 o;
            o.x = acc[jj * 4 + 0] * dinv; o.y = acc[jj * 4 + 1] * dinv;
            o.z = acc[jj * 4 + 2] * dinv; o.w = acc[jj * 4 + 3] * dinv;
            *(float4*)&g_at[(size_t)(t0 + t) * D_MODEL + col0 + e0 + jj * 4] = o;
        }
    }
}

// ---------------------------------------------------------------------------
extern "C" void kernel_launch(void* const* d_in, const int* in_sizes, int n_in,
                              void* d_out, int out_size)
{
    const float* x  = (const float*)d_in[0];
    const float* Wq = (const float*)d_in[1];
    const float* Wk = (const float*)d_in[2];
    const float* Wv = (const float*)d_in[3];
    const float* Wo = (const float*)d_in[4];
    const float* Wg = (const float*)d_in[5];
    const float* bg = (const float*)d_in[6];
    float* out = (float*)d_out;

    float *qb, *gb, *kb, *vb, *ab;
    cudaGetSymbolAddress((void**)&qb, g_q);
    cudaGetSymbolAddress((void**)&gb, g_g);
    cudaGetSymbolAddress((void**)&kb, g_kf);
    cudaGetSymbolAddress((void**)&vb, g_v);
    cudaGetSymbolAddress((void**)&ab, g_at);

    const int cs_smem = CHUNK * DH * 2 * sizeof(float);
    const int co_smem = CO_SMEM_FLOATS * sizeof(float);
    cudaFuncSetAttribute(chunk_state_kernel, cudaFuncAttributeMaxDynamicSharedMemorySize, cs_smem);
    cudaFuncSetAttribute(chunk_out_kernel,   cudaFuncAttributeMaxDynamicSharedMemorySize, co_smem);

    dim3 ggrid(D_MODEL / 128, T_SEQ / 128);  // (8, 16)

    gemm_nt_kernel<1><<<ggrid, 256>>>(x, Wq, nullptr, qb, T_SEQ, D_MODEL, D_MODEL);
    gemm_nt_kernel<1><<<ggrid, 256>>>(x, Wk, nullptr, kb, T_SEQ, D_MODEL, D_MODEL);
    gemm_nt_kernel<0><<<ggrid, 256>>>(x, Wv, nullptr, vb, T_SEQ, D_MODEL, D_MODEL);
    gemm_nt_kernel<2><<<ggrid, 256>>>(x, Wg, bg,      gb, T_SEQ, D_MODEL, D_MODEL);
    combine_qg_kernel<<<T_SEQ * D_MODEL / 256, 256>>>();

    chunk_state_kernel<<<NH * NCHUNK, 256, cs_smem>>>();
    prefix_kernel<<<NH, 256>>>(out);
    chunk_out_kernel<<<NH * NCHUNK, 256, co_smem>>>();

    gemm_nt_kernel<0><<<ggrid, 256>>>(ab, Wo, nullptr, out, T_SEQ, D_MODEL, D_MODEL);
}

// round 4
// speedup vs baseline: 1.9415x; 1.9415x over previous
#include <cuda_runtime.h>
#include <cuda_bf16.h>
#include <math.h>
#include <stdint.h>

#define T_SEQ   2048
#define D_MODEL 1024
#define NH      16
#define DH      64
#define CHUNK   128
#define NCHUNK  (T_SEQ / CHUNK)   // 16
#define KT      64                // K elems per SMEM chunk
#define NKC     (D_MODEL / KT)    // 16
#define NITER   (3 * NKC)         // 48 (3 split terms)
#define LDA     72                // SMEM row stride in bf16 elems (144B)

// ---------------- scratch (static __device__ arrays; no allocation) ----------
__device__ __align__(256) float g_q  [T_SEQ * D_MODEL];
__device__ __align__(256) float g_g  [T_SEQ * D_MODEL];
__device__ __align__(256) float g_kf [T_SEQ * D_MODEL];
__device__ __align__(256) float g_v  [T_SEQ * D_MODEL];
__device__ __align__(256) float g_at [T_SEQ * D_MODEL];
__device__ __align__(256) float g_Sc  [NH * NCHUNK * DH * DH];
__device__ __align__(256) float g_Spre[NH * NCHUNK * DH * DH];
__device__ __align__(256) float g_zc  [NH * NCHUNK * DH];
__device__ __align__(256) float g_zpre[NH * NCHUNK * DH];
__device__ __align__(256) __nv_bfloat16 g_xhi [T_SEQ * D_MODEL];
__device__ __align__(256) __nv_bfloat16 g_xlo [T_SEQ * D_MODEL];
__device__ __align__(256) __nv_bfloat16 g_Whi [5 * D_MODEL * D_MODEL];
__device__ __align__(256) __nv_bfloat16 g_Wlo [5 * D_MODEL * D_MODEL];
__device__ __align__(256) __nv_bfloat16 g_athi[T_SEQ * D_MODEL];
__device__ __align__(256) __nv_bfloat16 g_atlo[T_SEQ * D_MODEL];

__device__ __forceinline__ float softplus_f(float x) {
    return (x > 20.f) ? x : log1pf(expf(x));
}

// =============== split kernel: fp32 -> (hi, lo) bf16 ========================
__global__ __launch_bounds__(256) void split_kernel(const float* __restrict__ src,
                                                    __nv_bfloat16* __restrict__ hi,
                                                    __nv_bfloat16* __restrict__ lo, int n4) {
    int i = blockIdx.x * 256 + threadIdx.x;
    if (i >= n4) return;
    float4 v = ((const float4*)src)[i];
    __nv_bfloat16 h0 = __float2bfloat16_rn(v.x), h1 = __float2bfloat16_rn(v.y);
    __nv_bfloat16 h2 = __float2bfloat16_rn(v.z), h3 = __float2bfloat16_rn(v.w);
    __nv_bfloat162 H0; H0.x = h0; H0.y = h1;
    __nv_bfloat162 H1; H1.x = h2; H1.y = h3;
    __nv_bfloat162 L0, L1;
    L0.x = __float2bfloat16_rn(v.x - __bfloat162float(h0));
    L0.y = __float2bfloat16_rn(v.y - __bfloat162float(h1));
    L1.x = __float2bfloat16_rn(v.z - __bfloat162float(h2));
    L1.y = __float2bfloat16_rn(v.w - __bfloat162float(h3));
    ((__nv_bfloat162*)hi)[i * 2 + 0] = H0;
    ((__nv_bfloat162*)hi)[i * 2 + 1] = H1;
    ((__nv_bfloat162*)lo)[i * 2 + 0] = L0;
    ((__nv_bfloat162*)lo)[i * 2 + 1] = L1;
}

// ======== mma.sync split-bf16 GEMM: C[M,N] = A[M,K] * W[N,K]^T + act ========
// Block 128x128, 8 warps (2 in M x 4 in N), warp tile 64x32.
// grid = (N/128, M/128, nz); weight idx = wbase + z.
// mode: widx 0,1 -> softplus; 3 -> sigmoid(x+bias); else identity.
__global__ __launch_bounds__(256) void mma_gemm_kernel(
    const __nv_bfloat16* __restrict__ Ahi, const __nv_bfloat16* __restrict__ Alo,
    const float* __restrict__ bias,
    float* C0, float* C1, float* C2, float* C3, int wbase)
{
    extern __shared__ __nv_bfloat16 sm[];
    const int tid = threadIdx.x, lane = tid & 31, wid = tid >> 5;
    const int g = lane >> 2, t = lane & 3;
    const int warpM = (wid & 1) * 64, warpN = (wid >> 1) * 32;
    const int z = blockIdx.z, widx = wbase + z;
    const int m0 = blockIdx.y * 128, n0 = blockIdx.x * 128;

    const __nv_bfloat16* Wh = g_Whi + (size_t)widx * D_MODEL * D_MODEL;
    const __nv_bfloat16* Wl = g_Wlo + (size_t)widx * D_MODEL * D_MODEL;
    float* Cs[4] = {C0, C1, C2, C3};
    float* C = Cs[z];
    const int mode = (widx <= 1) ? 1 : (widx == 3 ? 2 : 0);

    float acc[4][4][4];
    #pragma unroll
    for (int a = 0; a < 4; a++)
        #pragma unroll
        for (int b = 0; b < 4; b++)
            #pragma unroll
            for (int c = 0; c < 4; c++) acc[a][b][c] = 0.f;

    const uint32_t smb = (uint32_t)__cvta_generic_to_shared(sm);
    // byte layout: A0 @0, A1 @18432, B0 @36864, B1 @55296  (each 128*72*2 = 18432B)

    auto issue = [&](int it, int buf) {
        const int term = it >> 4, kc = it & 15;
        const __nv_bfloat16* Ag = (term < 2) ? Ahi : Alo;
        const __nv_bfloat16* Bg = (term == 1) ? Wl : Wh;
        #pragma unroll
        for (int r = 0; r < 4; r++) {
            int id = tid + r * 256, row = id >> 3, c = id & 7;
            uint32_t da = smb + buf * 18432 + row * 144 + c * 16;
            const void* sa = Ag + (size_t)(m0 + row) * D_MODEL + kc * KT + c * 8;
            asm volatile("cp.async.cg.shared.global [%0], [%1], 16;" :: "r"(da), "l"(sa));
            uint32_t db = smb + 36864 + buf * 18432 + row * 144 + c * 16;
            const void* sb = Bg + (size_t)(n0 + row) * D_MODEL + kc * KT + c * 8;
            asm volatile("cp.async.cg.shared.global [%0], [%1], 16;" :: "r"(db), "l"(sb));
        }
        asm volatile("cp.async.commit_group;" ::: "memory");
    };

    issue(0, 0);
    for (int it = 0; it < NITER; it++) {
        const int buf = it & 1;
        if (it + 1 < NITER) {
            issue(it + 1, buf ^ 1);
            asm volatile("cp.async.wait_group 1;" ::: "memory");
        } else {
            asm volatile("cp.async.wait_group 0;" ::: "memory");
        }
        __syncthreads();

        const __nv_bfloat16* Ab = sm + buf * (128 * LDA);
        const __nv_bfloat16* Bb = sm + 2 * (128 * LDA) + buf * (128 * LDA);
        #pragma unroll
        for (int ks = 0; ks < 4; ks++) {
            const int kb = ks * 16;
            uint32_t af[4][4], bfr[4][2];
            #pragma unroll
            for (int mt = 0; mt < 4; mt++) {
                int r0 = warpM + mt * 16 + g;
                af[mt][0] = *(const uint32_t*)&Ab[(r0    ) * LDA + kb + 2 * t];
                af[mt][1] = *(const uint32_t*)&Ab[(r0 + 8) * LDA + kb + 2 * t];
                af[mt][2] = *(const uint32_t*)&Ab[(r0    ) * LDA + kb + 2 * t + 8];
                af[mt][3] = *(const uint32_t*)&Ab[(r0 + 8) * LDA + kb + 2 * t + 8];
            }
            #pragma unroll
            for (int nt = 0; nt < 4; nt++) {
                int rb = warpN + nt * 8 + g;
                bfr[nt][0] = *(const uint32_t*)&Bb[rb * LDA + kb + 2 * t];
                bfr[nt][1] = *(const uint32_t*)&Bb[rb * LDA + kb + 2 * t + 8];
            }
            #pragma unroll
            for (int mt = 0; mt < 4; mt++)
                #pragma unroll
                for (int nt = 0; nt < 4; nt++)
                    asm volatile(
                        "mma.sync.aligned.m16n8k16.row.col.f32.bf16.bf16.f32 "
                        "{%0,%1,%2,%3}, {%4,%5,%6,%7}, {%8,%9}, {%0,%1,%2,%3};"
                        : "+f"(acc[mt][nt][0]), "+f"(acc[mt][nt][1]),
                          "+f"(acc[mt][nt][2]), "+f"(acc[mt][nt][3])
                        : "r"(af[mt][0]), "r"(af[mt][1]), "r"(af[mt][2]), "r"(af[mt][3]),
                          "r"(bfr[nt][0]), "r"(bfr[nt][1]));
        }
        __syncthreads();
    }

    // ---------------- epilogue: activation + direct stores ------------------
    #pragma unroll
    for (int mt = 0; mt < 4; mt++) {
        int r0 = m0 + warpM + mt * 16 + g;
        #pragma unroll
        for (int nt = 0; nt < 4; nt++) {
            int c0 = n0 + warpN + nt * 8 + 2 * t;
            float v0 = acc[mt][nt][0], v1 = acc[mt][nt][1];
            float v2 = acc[mt][nt][2], v3 = acc[mt][nt][3];
            if (mode == 1) {
                v0 = softplus_f(v0); v1 = softplus_f(v1);
                v2 = softplus_f(v2); v3 = softplus_f(v3);
            } else if (mode == 2) {
                float b0 = __ldg(&bias[c0]), b1 = __ldg(&bias[c0 + 1]);
                v0 = 1.f / (1.f + expf(-(v0 + b0)));
                v1 = 1.f / (1.f + expf(-(v1 + b1)));
                v2 = 1.f / (1.f + expf(-(v2 + b0)));
                v3 = 1.f / (1.f + expf(-(v3 + b1)));
            }
            float2 p0; p0.x = v0; p0.y = v1;
            float2 p1; p1.x = v2; p1.y = v3;
            *(float2*)&C[(size_t)r0 * D_MODEL + c0]       = p0;
            *(float2*)&C[(size_t)(r0 + 8) * D_MODEL + c0] = p1;
        }
    }
}

// qf = softplus(q) * (sigmoid(gate) + 1e-6)
__global__ void combine_qg_kernel() {
    int i = blockIdx.x * 256 + threadIdx.x;
    g_q[i] = g_q[i] * (g_g[i] + 1e-6f);
}

// ------------- per-(head,chunk) local state S_c = Kf^T V, z_c = sum kf ------
__global__ __launch_bounds__(256) void chunk_state_kernel() {
    extern __shared__ float smf[];
    float* Kc = smf;
    float* Vc = smf + CHUNK * DH;
    const int head = blockIdx.x >> 4, chunk = blockIdx.x & 15;
    const int t0 = chunk * CHUNK, col0 = head * DH;
    const int tid = threadIdx.x;

    for (int i = tid; i < CHUNK * DH / 4; i += 256) {
        int tt = i >> 4, c4 = (i & 15) << 2;
        *(float4*)&Kc[tt * DH + c4] = *(const float4*)&g_kf[(size_t)(t0 + tt) * D_MODEL + col0 + c4];
        *(float4*)&Vc[tt * DH + c4] = *(const float4*)&g_v [(size_t)(t0 + tt) * D_MODEL + col0 + c4];
    }
    __syncthreads();

    const int d = tid >> 2, e0 = (tid & 3) << 4;
    float acc[16] = {};
    float z = 0.f;
    for (int tt = 0; tt < CHUNK; tt++) {
        float kv = Kc[tt * DH + d];
        z += kv;
        #pragma unroll
        for (int jj = 0; jj < 4; jj++) {
            float4 vv = *(float4*)&Vc[tt * DH + e0 + jj * 4];
            acc[jj * 4 + 0] = fmaf(kv, vv.x, acc[jj * 4 + 0]);
            acc[jj * 4 + 1] = fmaf(kv, vv.y, acc[jj * 4 + 1]);
            acc[jj * 4 + 2] = fmaf(kv, vv.z, acc[jj * 4 + 2]);
            acc[jj * 4 + 3] = fmaf(kv, vv.w, acc[jj * 4 + 3]);
        }
    }
    size_t base = (size_t)blockIdx.x * (DH * DH);
    #pragma unroll
    for (int j = 0; j < 16; j++) g_Sc[base + d * DH + e0 + j] = acc[j];
    if ((tid & 3) == 0) g_zc[blockIdx.x * DH + d] = z;
}

// ------------- sequential prefix over the 16 chunks (per head) --------------
__global__ __launch_bounds__(256) void prefix_kernel(float* __restrict__ out) {
    const int head = blockIdx.x, tid = threadIdx.x;
    float acc[16] = {};
    for (int c = 0; c < NCHUNK; c++) {
        size_t base = ((size_t)head * NCHUNK + c) * (DH * DH);
        #pragma unroll
        for (int k = 0; k < 16; k++) {
            g_Spre[base + tid + k * 256] = acc[k];
            acc[k] += g_Sc[base + tid + k * 256];
        }
    }
    float* kv_out = out + (size_t)T_SEQ * D_MODEL;
    #pragma unroll
    for (int k = 0; k < 16; k++)
        kv_out[(size_t)head * DH * DH + tid + k * 256] = acc[k];

    if (tid < DH) {
        float z = 0.f;
        for (int c = 0; c < NCHUNK; c++) {
            int base = (head * NCHUNK + c) * DH;
            g_zpre[base + tid] = z;
            z += g_zc[base + tid];
        }
        float* z_out = out + (size_t)T_SEQ * D_MODEL + NH * DH * DH;
        z_out[head * DH + tid] = z;
    }
}

// ------------- per-(head,chunk) output: causal intra + inter via S_prefix ---
#define QT_STRIDE 132
#define AS_STRIDE 132
#define CO_SMEM_FLOATS (DH*QT_STRIDE*2 + CHUNK*DH + DH*DH + CHUNK*AS_STRIDE + DH + CHUNK)

__global__ __launch_bounds__(256) void chunk_out_kernel() {
    extern __shared__ float smf[];
    float* Qt  = smf;
    float* Kt  = Qt + DH * QT_STRIDE;
    float* Vs  = Kt + DH * QT_STRIDE;
    float* Ss  = Vs + CHUNK * DH;
    float* As  = Ss + DH * DH;
    float* zs  = As + CHUNK * AS_STRIDE;
    float* den = zs + DH;
    const int head = blockIdx.x >> 4, chunk = blockIdx.x & 15;
    const int t0 = chunk * CHUNK, col0 = head * DH;
    const int tid = threadIdx.x;

    for (int i = tid; i < CHUNK * DH / 4; i += 256) {
        int tt = i >> 4, c4 = (i & 15) << 2;
        float4 q4 = *(const float4*)&g_q [(size_t)(t0 + tt) * D_MODEL + col0 + c4];
        Qt[(c4 + 0) * QT_STRIDE + tt] = q4.x; Qt[(c4 + 1) * QT_STRIDE + tt] = q4.y;
        Qt[(c4 + 2) * QT_STRIDE + tt] = q4.z; Qt[(c4 + 3) * QT_STRIDE + tt] = q4.w;
        float4 k4 = *(const float4*)&g_kf[(size_t)(t0 + tt) * D_MODEL + col0 + c4];
        Kt[(c4 + 0) * QT_STRIDE + tt] = k4.x; Kt[(c4 + 1) * QT_STRIDE + tt] = k4.y;
        Kt[(c4 + 2) * QT_STRIDE + tt] = k4.z; Kt[(c4 + 3) * QT_STRIDE + tt] = k4.w;
        *(float4*)&Vs[tt * DH + c4] = *(const float4*)&g_v[(size_t)(t0 + tt) * D_MODEL + col0 + c4];
    }
    {
        size_t base = ((size_t)head * NCHUNK + chunk) * (DH * DH);
        for (int i = tid; i < DH * DH / 4; i += 256)
            *(float4*)&Ss[i * 4] = *(const float4*)&g_Spre[base + i * 4];
    }
    if (tid < DH)    zs[tid]  = g_zpre[(head * NCHUNK + chunk) * DH + tid];
    if (tid < CHUNK) den[tid] = 0.f;
    __syncthreads();

    {
        const int tx = tid & 15, ty = tid >> 4;
        float a[8][8] = {};
        for (int k = 0; k < DH; k++) {
            float qr[8], kr[8];
            *(float4*)&qr[0] = *(float4*)&Qt[k * QT_STRIDE + ty * 8];
            *(float4*)&qr[4] = *(float4*)&Qt[k * QT_STRIDE + ty * 8 + 4];
            *(float4*)&kr[0] = *(float4*)&Kt[k * QT_STRIDE + tx * 8];
            *(float4*)&kr[4] = *(float4*)&Kt[k * QT_STRIDE + tx * 8 + 4];
            #pragma unroll
            for (int i = 0; i < 8; i++)
                #pragma unroll
                for (int j = 0; j < 8; j++)
                    a[i][j] = fmaf(qr[i], kr[j], a[i][j]);
        }
        #pragma unroll
        for (int i = 0; i < 8; i++) {
            int tr = ty * 8 + i;
            float rs = 0.f;
            #pragma unroll
            for (int j = 0; j < 8; j++) {
                int s = tx * 8 + j;
                float vv = (s <= tr) ? a[i][j] : 0.f;
                As[tr * AS_STRIDE + s] = vv;
                rs += vv;
            }
            atomicAdd(&den[tr], rs);
        }
    }
    __syncthreads();
    if (tid < CHUNK) {
        float dz = 0.f;
        #pragma unroll 8
        for (int d = 0; d < DH; d++) dz += Qt[d * QT_STRIDE + tid] * zs[d];
        den[tid] += dz + 1e-6f;
    }
    __syncthreads();

    {
        const int tr = tid & 127;
        const int e0 = (tid >> 7) * 32;
        float acc[32] = {};
        for (int d = 0; d < DH; d++) {
            float qv = Qt[d * QT_STRIDE + tr];
            #pragma unroll
            for (int jj = 0; jj < 8; jj++) {
                float4 sv = *(float4*)&Ss[d * DH + e0 + jj * 4];
                acc[jj * 4 + 0] = fmaf(qv, sv.x, acc[jj * 4 + 0]);
                acc[jj * 4 + 1] = fmaf(qv, sv.y, acc[jj * 4 + 1]);
                acc[jj * 4 + 2] = fmaf(qv, sv.z, acc[jj * 4 + 2]);
                acc[jj * 4 + 3] = fmaf(qv, sv.w, acc[jj * 4 + 3]);
            }
        }
        for (int s = 0; s < CHUNK; s++) {
            float av = As[tr * AS_STRIDE + s];
            #pragma unroll
            for (int jj = 0; jj < 8; jj++) {
                float4 vv = *(float4*)&Vs[s * DH + e0 + jj * 4];
                acc[jj * 4 + 0] = fmaf(av, vv.x, acc[jj * 4 + 0]);
                acc[jj * 4 + 1] = fmaf(av, vv.y, acc[jj * 4 + 1]);
                acc[jj * 4 + 2] = fmaf(av, vv.z, acc[jj * 4 + 2]);
                acc[jj * 4 + 3] = fmaf(av, vv.w, acc[jj * 4 + 3]);
            }
        }
        float dinv = 1.f / den[tr];
        #pragma unroll
        for (int jj = 0; jj < 8; jj++) {
            float4 o;
            o.x = acc[jj * 4 + 0] * dinv; o.y = acc[jj * 4 + 1] * dinv;
            o.z = acc[jj * 4 + 2] * dinv; o.w = acc[jj * 4 + 3] * dinv;
            *(float4*)&g_at[(size_t)(t0 + tr) * D_MODEL + col0 + e0 + jj * 4] = o;
        }
    }
}

// ---------------------------------------------------------------------------
extern "C" void kernel_launch(void* const* d_in, const int* in_sizes, int n_in,
                              void* d_out, int out_size)
{
    const float* x  = (const float*)d_in[0];
    const float* W[5] = { (const float*)d_in[1], (const float*)d_in[2],
                          (const float*)d_in[3], (const float*)d_in[5],   // Wq,Wk,Wv,Wg
                          (const float*)d_in[4] };                        // Wo at slot 4
    const float* bg = (const float*)d_in[6];
    float* out = (float*)d_out;

    float *qb, *gb, *kb, *vb, *ab;
    cudaGetSymbolAddress((void**)&qb, g_q);
    cudaGetSymbolAddress((void**)&gb, g_g);
    cudaGetSymbolAddress((void**)&kb, g_kf);
    cudaGetSymbolAddress((void**)&vb, g_v);
    cudaGetSymbolAddress((void**)&ab, g_at);
    __nv_bfloat16 *xhi, *xlo, *whi, *wlo, *athi, *atlo;
    cudaGetSymbolAddress((void**)&xhi, g_xhi);
    cudaGetSymbolAddress((void**)&xlo, g_xlo);
    cudaGetSymbolAddress((void**)&whi, g_Whi);
    cudaGetSymbolAddress((void**)&wlo, g_Wlo);
    cudaGetSymbolAddress((void**)&athi, g_athi);
    cudaGetSymbolAddress((void**)&atlo, g_atlo);

    const int cs_smem = CHUNK * DH * 2 * sizeof(float);
    const int co_smem = CO_SMEM_FLOATS * sizeof(float);
    const int gm_smem = 4 * 128 * LDA * sizeof(__nv_bfloat16);   // 73728 B
    cudaFuncSetAttribute(chunk_state_kernel, cudaFuncAttributeMaxDynamicSharedMemorySize, cs_smem);
    cudaFuncSetAttribute(chunk_out_kernel,   cudaFuncAttributeMaxDynamicSharedMemorySize, co_smem);
    cudaFuncSetAttribute(mma_gemm_kernel,    cudaFuncAttributeMaxDynamicSharedMemorySize, gm_smem);

    // 1) split x and the 5 weights into bf16 hi/lo
    split_kernel<<<T_SEQ * D_MODEL / 1024, 256>>>(x, xhi, xlo, T_SEQ * D_MODEL / 4);
    for (int i = 0; i < 5; i++)
        split_kernel<<<D_MODEL * D_MODEL / 1024, 256>>>(
            W[i], whi + (size_t)i * D_MODEL * D_MODEL, wlo + (size_t)i * D_MODEL * D_MODEL,
            D_MODEL * D_MODEL / 4);

    // 2) fused Q/K/V/G projections (weight slots 0..3)
    {
        dim3 grid(D_MODEL / 128, T_SEQ / 128, 4);
        mma_gemm_kernel<<<grid, 256, gm_smem>>>(xhi, xlo, bg, qb, kb, vb, gb, 0);
    }
    combine_qg_kernel<<<T_SEQ * D_MODEL / 256, 256>>>();

    // 3) attention chunk pipeline (fp32)
    chunk_state_kernel<<<NH * NCHUNK, 256, cs_smem>>>();
    prefix_kernel<<<NH, 256>>>(out);
    chunk_out_kernel<<<NH * NCHUNK, 256, co_smem>>>();

    // 4) output projection (weight slot 4)
    split_kernel<<<T_SEQ * D_MODEL / 1024, 256>>>(ab, athi, atlo, T_SEQ * D_MODEL / 4);
    {
        dim3 grid(D_MODEL / 128, T_SEQ / 128, 1);
        mma_gemm_kernel<<<grid, 256, gm_smem>>>(athi, atlo, nullptr, out, out, out, out, 4);
    }
}

// round 5
// speedup vs baseline: 1.9987x; 1.0295x over previous
#include <cuda_runtime.h>
#include <cuda_bf16.h>
#include <math.h>
#include <stdint.h>

#define T_SEQ   2048
#define D_MODEL 1024
#define NH      16
#define DH      64
#define CHUNK   128
#define NCHUNK  (T_SEQ / CHUNK)   // 16
#define KT      64                // K elems per SMEM chunk
#define NKC     (D_MODEL / KT)    // 16
#define NITER   (3 * NKC)         // 48 (3 split terms)
#define LDAE    72                // SMEM row stride in bf16 elems (144B)
#define STAGE_BYTES 36864         // (A 128*144) + (B 128*144)
#define NSTAGE  3

// ---------------- scratch (static __device__ arrays; no allocation) ----------
__device__ __align__(256) float g_q  [T_SEQ * D_MODEL];
__device__ __align__(256) float g_g  [T_SEQ * D_MODEL];
__device__ __align__(256) float g_kf [T_SEQ * D_MODEL];
__device__ __align__(256) float g_v  [T_SEQ * D_MODEL];
__device__ __align__(256) float g_at [T_SEQ * D_MODEL];
__device__ __align__(256) float g_Sc  [NH * NCHUNK * DH * DH];
__device__ __align__(256) float g_Spre[NH * NCHUNK * DH * DH];
__device__ __align__(256) float g_zc  [NH * NCHUNK * DH];
__device__ __align__(256) float g_zpre[NH * NCHUNK * DH];
__device__ __align__(256) __nv_bfloat16 g_xhi [T_SEQ * D_MODEL];
__device__ __align__(256) __nv_bfloat16 g_xlo [T_SEQ * D_MODEL];
__device__ __align__(256) __nv_bfloat16 g_Whi [5 * D_MODEL * D_MODEL];
__device__ __align__(256) __nv_bfloat16 g_Wlo [5 * D_MODEL * D_MODEL];
__device__ __align__(256) __nv_bfloat16 g_athi[T_SEQ * D_MODEL];
__device__ __align__(256) __nv_bfloat16 g_atlo[T_SEQ * D_MODEL];

__device__ __forceinline__ float softplus_f(float x) {
    return (x > 20.f) ? x : log1pf(expf(x));
}

// =============== split kernel: fp32 -> (hi, lo) bf16 ========================
__global__ __launch_bounds__(256) void split_kernel(const float* __restrict__ src,
                                                    __nv_bfloat16* __restrict__ hi,
                                                    __nv_bfloat16* __restrict__ lo, int n4) {
    int i = blockIdx.x * 256 + threadIdx.x;
    if (i >= n4) return;
    float4 v = ((const float4*)src)[i];
    __nv_bfloat16 h0 = __float2bfloat16_rn(v.x), h1 = __float2bfloat16_rn(v.y);
    __nv_bfloat16 h2 = __float2bfloat16_rn(v.z), h3 = __float2bfloat16_rn(v.w);
    __nv_bfloat162 H0; H0.x = h0; H0.y = h1;
    __nv_bfloat162 H1; H1.x = h2; H1.y = h3;
    __nv_bfloat162 L0, L1;
    L0.x = __float2bfloat16_rn(v.x - __bfloat162float(h0));
    L0.y = __float2bfloat16_rn(v.y - __bfloat162float(h1));
    L1.x = __float2bfloat16_rn(v.z - __bfloat162float(h2));
    L1.y = __float2bfloat16_rn(v.w - __bfloat162float(h3));
    ((__nv_bfloat162*)hi)[i * 2 + 0] = H0;
    ((__nv_bfloat162*)hi)[i * 2 + 1] = H1;
    ((__nv_bfloat162*)lo)[i * 2 + 0] = L0;
    ((__nv_bfloat162*)lo)[i * 2 + 1] = L1;
}

// ======== mma.sync split-bf16 GEMM: C[M,N] = A[M,K] * W[N,K]^T + act ========
// Block 128x128, 8 warps (2 in M x 4 in N), warp tile 64x32, ldmatrix frags,
// 3-stage cp.async pipeline.
__global__ __launch_bounds__(256) void mma_gemm_kernel(
    const __nv_bfloat16* __restrict__ Ahi, const __nv_bfloat16* __restrict__ Alo,
    const float* __restrict__ bias,
    float* C0, float* C1, float* C2, float* C3, int wbase)
{
    extern __shared__ __nv_bfloat16 sm[];
    const int tid = threadIdx.x, lane = tid & 31, wid = tid >> 5;
    const int g = lane >> 2, t = lane & 3;
    const int warpM = (wid & 1) * 64, warpN = (wid >> 1) * 32;
    const int z = blockIdx.z, widx = wbase + z;
    const int m0 = blockIdx.y * 128, n0 = blockIdx.x * 128;

    const __nv_bfloat16* Wh = g_Whi + (size_t)widx * D_MODEL * D_MODEL;
    const __nv_bfloat16* Wl = g_Wlo + (size_t)widx * D_MODEL * D_MODEL;
    float* Cs[4] = {C0, C1, C2, C3};
    float* C = Cs[z];
    const int mode = (widx <= 1) ? 1 : (widx == 3 ? 2 : 0);

    float acc[4][4][4];
    #pragma unroll
    for (int a = 0; a < 4; a++)
        #pragma unroll
        for (int b = 0; b < 4; b++)
            #pragma unroll
            for (int c = 0; c < 4; c++) acc[a][b][c] = 0.f;

    const uint32_t smb = (uint32_t)__cvta_generic_to_shared(sm);

    // ldmatrix per-lane address components
    const int q8   = lane & 7;
    const int ah   = (lane >> 3) & 1;   // A: row half select
    const int akh  = lane >> 4;         // A: k half select
    const int bidx = lane >> 3;         // B: matrix index 0..3
    const uint32_t aOff = (uint32_t)((warpM + ah * 8 + q8) * 144 + akh * 16);
    const uint32_t bOff = (uint32_t)(18432 + (warpN + (bidx >> 1) * 8 + q8) * 144 + (bidx & 1) * 16);

    auto issue = [&](int it) {
        const int st = it % NSTAGE;
        const int term = it >> 4, kc = it & 15;
        const __nv_bfloat16* Ag = (term < 2) ? Ahi : Alo;
        const __nv_bfloat16* Bg = (term == 1) ? Wl : Wh;
        const uint32_t sbase = smb + st * STAGE_BYTES;
        #pragma unroll
        for (int r = 0; r < 4; r++) {
            int id = tid + r * 256, row = id >> 3, c = id & 7;
            uint32_t da = sbase + row * 144 + c * 16;
            const void* sa = Ag + (size_t)(m0 + row) * D_MODEL + kc * KT + c * 8;
            asm volatile("cp.async.cg.shared.global [%0], [%1], 16;" :: "r"(da), "l"(sa));
            uint32_t db = sbase + 18432 + row * 144 + c * 16;
            const void* sb = Bg + (size_t)(n0 + row) * D_MODEL + kc * KT + c * 8;
            asm volatile("cp.async.cg.shared.global [%0], [%1], 16;" :: "r"(db), "l"(sb));
        }
        asm volatile("cp.async.commit_group;" ::: "memory");
    };

    issue(0); issue(1); issue(2);

    for (int it = 0; it < NITER; it++) {
        if (it < NITER - 2)       asm volatile("cp.async.wait_group 2;" ::: "memory");
        else if (it == NITER - 2) asm volatile("cp.async.wait_group 1;" ::: "memory");
        else                      asm volatile("cp.async.wait_group 0;" ::: "memory");
        __syncthreads();

        const uint32_t sbase = smb + (it % NSTAGE) * STAGE_BYTES;
        #pragma unroll
        for (int ks = 0; ks < 4; ks++) {
            uint32_t af[4][4], bfr[4][2];
            #pragma unroll
            for (int mt = 0; mt < 4; mt++) {
                uint32_t addr = sbase + aOff + mt * (16 * 144) + ks * 32;
                asm volatile("ldmatrix.sync.aligned.m8n8.x4.shared.b16 {%0,%1,%2,%3}, [%4];"
                             : "=r"(af[mt][0]), "=r"(af[mt][1]), "=r"(af[mt][2]), "=r"(af[mt][3])
                             : "r"(addr));
            }
            #pragma unroll
            for (int p = 0; p < 2; p++) {
                uint32_t addr = sbase + bOff + p * (16 * 144) + ks * 32;
                asm volatile("ldmatrix.sync.aligned.m8n8.x4.shared.b16 {%0,%1,%2,%3}, [%4];"
                             : "=r"(bfr[2 * p][0]), "=r"(bfr[2 * p][1]),
                               "=r"(bfr[2 * p + 1][0]), "=r"(bfr[2 * p + 1][1])
                             : "r"(addr));
            }
            #pragma unroll
            for (int mt = 0; mt < 4; mt++)
                #pragma unroll
                for (int nt = 0; nt < 4; nt++)
                    asm volatile(
                        "mma.sync.aligned.m16n8k16.row.col.f32.bf16.bf16.f32 "
                        "{%0,%1,%2,%3}, {%4,%5,%6,%7}, {%8,%9}, {%0,%1,%2,%3};"
                        : "+f"(acc[mt][nt][0]), "+f"(acc[mt][nt][1]),
                          "+f"(acc[mt][nt][2]), "+f"(acc[mt][nt][3])
                        : "r"(af[mt][0]), "r"(af[mt][1]), "r"(af[mt][2]), "r"(af[mt][3]),
                          "r"(bfr[nt][0]), "r"(bfr[nt][1]));
        }
        __syncthreads();
        if (it + NSTAGE < NITER) issue(it + NSTAGE);
    }

    // ---------------- epilogue: activation + direct stores ------------------
    #pragma unroll
    for (int mt = 0; mt < 4; mt++) {
        int r0 = m0 + warpM + mt * 16 + g;
        #pragma unroll
        for (int nt = 0; nt < 4; nt++) {
            int c0 = n0 + warpN + nt * 8 + 2 * t;
            float v0 = acc[mt][nt][0], v1 = acc[mt][nt][1];
            float v2 = acc[mt][nt][2], v3 = acc[mt][nt][3];
            if (mode == 1) {
                v0 = softplus_f(v0); v1 = softplus_f(v1);
                v2 = softplus_f(v2); v3 = softplus_f(v3);
            } else if (mode == 2) {
                float b0 = __ldg(&bias[c0]), b1 = __ldg(&bias[c0 + 1]);
                v0 = 1.f / (1.f + expf(-(v0 + b0)));
                v1 = 1.f / (1.f + expf(-(v1 + b1)));
                v2 = 1.f / (1.f + expf(-(v2 + b0)));
                v3 = 1.f / (1.f + expf(-(v3 + b1)));
            }
            float2 p0; p0.x = v0; p0.y = v1;
            float2 p1; p1.x = v2; p1.y = v3;
            *(float2*)&C[(size_t)r0 * D_MODEL + c0]       = p0;
            *(float2*)&C[(size_t)(r0 + 8) * D_MODEL + c0] = p1;
        }
    }
}

// qf = softplus(q) * (sigmoid(gate) + 1e-6)
__global__ void combine_qg_kernel() {
    int i = blockIdx.x * 256 + threadIdx.x;
    g_q[i] = g_q[i] * (g_g[i] + 1e-6f);
}

// ------------- per-(head,chunk) local state S_c = Kf^T V, z_c = sum kf ------
__global__ __launch_bounds__(256) void chunk_state_kernel() {
    extern __shared__ float smf[];
    float* Kc = smf;
    float* Vc = smf + CHUNK * DH;
    const int head = blockIdx.x >> 4, chunk = blockIdx.x & 15;
    const int t0 = chunk * CHUNK, col0 = head * DH;
    const int tid = threadIdx.x;

    for (int i = tid; i < CHUNK * DH / 4; i += 256) {
        int tt = i >> 4, c4 = (i & 15) << 2;
        *(float4*)&Kc[tt * DH + c4] = *(const float4*)&g_kf[(size_t)(t0 + tt) * D_MODEL + col0 + c4];
        *(float4*)&Vc[tt * DH + c4] = *(const float4*)&g_v [(size_t)(t0 + tt) * D_MODEL + col0 + c4];
    }
    __syncthreads();

    const int d = tid >> 2, e0 = (tid & 3) << 4;
    float acc[16] = {};
    float z = 0.f;
    for (int tt = 0; tt < CHUNK; tt++) {
        float kv = Kc[tt * DH + d];
        z += kv;
        #pragma unroll
        for (int jj = 0; jj < 4; jj++) {
            float4 vv = *(float4*)&Vc[tt * DH + e0 + jj * 4];
            acc[jj * 4 + 0] = fmaf(kv, vv.x, acc[jj * 4 + 0]);
            acc[jj * 4 + 1] = fmaf(kv, vv.y, acc[jj * 4 + 1]);
            acc[jj * 4 + 2] = fmaf(kv, vv.z, acc[jj * 4 + 2]);
            acc[jj * 4 + 3] = fmaf(kv, vv.w, acc[jj * 4 + 3]);
        }
    }
    size_t base = (size_t)blockIdx.x * (DH * DH);
    #pragma unroll
    for (int j = 0; j < 16; j++) g_Sc[base + d * DH + e0 + j] = acc[j];
    if ((tid & 3) == 0) g_zc[blockIdx.x * DH + d] = z;
}

// ------------- sequential prefix over the 16 chunks (per head) --------------
__global__ __launch_bounds__(256) void prefix_kernel(float* __restrict__ out) {
    const int head = blockIdx.x, tid = threadIdx.x;
    float acc[16] = {};
    for (int c = 0; c < NCHUNK; c++) {
        size_t base = ((size_t)head * NCHUNK + c) * (DH * DH);
        #pragma unroll
        for (int k = 0; k < 16; k++) {
            g_Spre[base + tid + k * 256] = acc[k];
            acc[k] += g_Sc[base + tid + k * 256];
        }
    }
    float* kv_out = out + (size_t)T_SEQ * D_MODEL;
    #pragma unroll
    for (int k = 0; k < 16; k++)
        kv_out[(size_t)head * DH * DH + tid + k * 256] = acc[k];

    if (tid < DH) {
        float z = 0.f;
        for (int c = 0; c < NCHUNK; c++) {
            int base = (head * NCHUNK + c) * DH;
            g_zpre[base + tid] = z;
            z += g_zc[base + tid];
        }
        float* z_out = out + (size_t)T_SEQ * D_MODEL + NH * DH * DH;
        z_out[head * DH + tid] = z;
    }
}

// ------------- per-(head,chunk) output: causal intra + inter via S_prefix ---
#define QT_STRIDE 132
#define AS_STRIDE 132
#define CO_SMEM_FLOATS (DH*QT_STRIDE*2 + CHUNK*DH + DH*DH + CHUNK*AS_STRIDE + DH + CHUNK)

__global__ __launch_bounds__(256) void chunk_out_kernel() {
    extern __shared__ float smf[];
    float* Qt  = smf;
    float* Kt  = Qt + DH * QT_STRIDE;
    float* Vs  = Kt + DH * QT_STRIDE;
    float* Ss  = Vs + CHUNK * DH;
    float* As  = Ss + DH * DH;
    float* zs  = As + CHUNK * AS_STRIDE;
    float* den = zs + DH;
    const int head = blockIdx.x >> 4, chunk = blockIdx.x & 15;
    const int t0 = chunk * CHUNK, col0 = head * DH;
    const int tid = threadIdx.x;

    for (int i = tid; i < CHUNK * DH / 4; i += 256) {
        int tt = i >> 4, c4 = (i & 15) << 2;
        float4 q4 = *(const float4*)&g_q [(size_t)(t0 + tt) * D_MODEL + col0 + c4];
        Qt[(c4 + 0) * QT_STRIDE + tt] = q4.x; Qt[(c4 + 1) * QT_STRIDE + tt] = q4.y;
        Qt[(c4 + 2) * QT_STRIDE + tt] = q4.z; Qt[(c4 + 3) * QT_STRIDE + tt] = q4.w;
        float4 k4 = *(const float4*)&g_kf[(size_t)(t0 + tt) * D_MODEL + col0 + c4];
        Kt[(c4 + 0) * QT_STRIDE + tt] = k4.x; Kt[(c4 + 1) * QT_STRIDE + tt] = k4.y;
        Kt[(c4 + 2) * QT_STRIDE + tt] = k4.z; Kt[(c4 + 3) * QT_STRIDE + tt] = k4.w;
        *(float4*)&Vs[tt * DH + c4] = *(const float4*)&g_v[(size_t)(t0 + tt) * D_MODEL + col0 + c4];
    }
    {
        size_t base = ((size_t)head * NCHUNK + chunk) * (DH * DH);
        for (int i = tid; i < DH * DH / 4; i += 256)
            *(float4*)&Ss[i * 4] = *(const float4*)&g_Spre[base + i * 4];
    }
    if (tid < DH)    zs[tid]  = g_zpre[(head * NCHUNK + chunk) * DH + tid];
    if (tid < CHUNK) den[tid] = 0.f;
    __syncthreads();

    {
        const int tx = tid & 15, ty = tid >> 4;
        float a[8][8] = {};
        for (int k = 0; k < DH; k++) {
            float qr[8], kr[8];
            *(float4*)&qr[0] = *(float4*)&Qt[k * QT_STRIDE + ty * 8];
            *(float4*)&qr[4] = *(float4*)&Qt[k * QT_STRIDE + ty * 8 + 4];
            *(float4*)&kr[0] = *(float4*)&Kt[k * QT_STRIDE + tx * 8];
            *(float4*)&kr[4] = *(float4*)&Kt[k * QT_STRIDE + tx * 8 + 4];
            #pragma unroll
            for (int i = 0; i < 8; i++)
                #pragma unroll
                for (int j = 0; j < 8; j++)
                    a[i][j] = fmaf(qr[i], kr[j], a[i][j]);
        }
        #pragma unroll
        for (int i = 0; i < 8; i++) {
            int tr = ty * 8 + i;
            float rs = 0.f;
            #pragma unroll
            for (int j = 0; j < 8; j++) {
                int s = tx * 8 + j;
                float vv = (s <= tr) ? a[i][j] : 0.f;
                As[tr * AS_STRIDE + s] = vv;
                rs += vv;
            }
            atomicAdd(&den[tr], rs);
        }
    }
    __syncthreads();
    if (tid < CHUNK) {
        float dz = 0.f;
        #pragma unroll 8
        for (int d = 0; d < DH; d++) dz += Qt[d * QT_STRIDE + tid] * zs[d];
        den[tid] += dz + 1e-6f;
    }
    __syncthreads();

    {
        const int tr = tid & 127;
        const int e0 = (tid >> 7) * 32;
        float acc[32] = {};
        for (int d = 0; d < DH; d++) {
            float qv = Qt[d * QT_STRIDE + tr];
            #pragma unroll
            for (int jj = 0; jj < 8; jj++) {
                float4 sv = *(float4*)&Ss[d * DH + e0 + jj * 4];
                acc[jj * 4 + 0] = fmaf(qv, sv.x, acc[jj * 4 + 0]);
                acc[jj * 4 + 1] = fmaf(qv, sv.y, acc[jj * 4 + 1]);
                acc[jj * 4 + 2] = fmaf(qv, sv.z, acc[jj * 4 + 2]);
                acc[jj * 4 + 3] = fmaf(qv, sv.w, acc[jj * 4 + 3]);
            }
        }
        for (int s = 0; s < CHUNK; s++) {
            float av = As[tr * AS_STRIDE + s];
            #pragma unroll
            for (int jj = 0; jj < 8; jj++) {
                float4 vv = *(float4*)&Vs[s * DH + e0 + jj * 4];
                acc[jj * 4 + 0] = fmaf(av, vv.x, acc[jj * 4 + 0]);
                acc[jj * 4 + 1] = fmaf(av, vv.y, acc[jj * 4 + 1]);
                acc[jj * 4 + 2] = fmaf(av, vv.z, acc[jj * 4 + 2]);
                acc[jj * 4 + 3] = fmaf(av, vv.w, acc[jj * 4 + 3]);
            }
        }
        float dinv = 1.f / den[tr];
        #pragma unroll
        for (int jj = 0; jj < 8; jj++) {
            float4 o;
            o.x = acc[jj * 4 + 0] * dinv; o.y = acc[jj * 4 + 1] * dinv;
            o.z = acc[jj * 4 + 2] * dinv; o.w = acc[jj * 4 + 3] * dinv;
            *(float4*)&g_at[(size_t)(t0 + tr) * D_MODEL + col0 + e0 + jj * 4] = o;
        }
    }
}

// ---------------------------------------------------------------------------
extern "C" void kernel_launch(void* const* d_in, const int* in_sizes, int n_in,
                              void* d_out, int out_size)
{
    const float* x  = (const float*)d_in[0];
    const float* W[5] = { (const float*)d_in[1], (const float*)d_in[2],
                          (const float*)d_in[3], (const float*)d_in[5],   // Wq,Wk,Wv,Wg
                          (const float*)d_in[4] };                        // Wo at slot 4
    const float* bg = (const float*)d_in[6];
    float* out = (float*)d_out;

    float *qb, *gb, *kb, *vb, *ab;
    cudaGetSymbolAddress((void**)&qb, g_q);
    cudaGetSymbolAddress((void**)&gb, g_g);
    cudaGetSymbolAddress((void**)&kb, g_kf);
    cudaGetSymbolAddress((void**)&vb, g_v);
    cudaGetSymbolAddress((void**)&ab, g_at);
    __nv_bfloat16 *xhi, *xlo, *whi, *wlo, *athi, *atlo;
    cudaGetSymbolAddress((void**)&xhi, g_xhi);
    cudaGetSymbolAddress((void**)&xlo, g_xlo);
    cudaGetSymbolAddress((void**)&whi, g_Whi);
    cudaGetSymbolAddress((void**)&wlo, g_Wlo);
    cudaGetSymbolAddress((void**)&athi, g_athi);
    cudaGetSymbolAddress((void**)&atlo, g_atlo);

    const int cs_smem = CHUNK * DH * 2 * sizeof(float);
    const int co_smem = CO_SMEM_FLOATS * sizeof(float);
    const int gm_smem = NSTAGE * STAGE_BYTES;   // 110592 B
    cudaFuncSetAttribute(chunk_state_kernel, cudaFuncAttributeMaxDynamicSharedMemorySize, cs_smem);
    cudaFuncSetAttribute(chunk_out_kernel,   cudaFuncAttributeMaxDynamicSharedMemorySize, co_smem);
    cudaFuncSetAttribute(mma_gemm_kernel,    cudaFuncAttributeMaxDynamicSharedMemorySize, gm_smem);

    // 1) splits needed for QKVG: x + W0..W3 (5 launches -> QKVG is launch idx 5,
    //    which is what ncu -s 5 -c 1 captures)
    split_kernel<<<T_SEQ * D_MODEL / 1024, 256>>>(x, xhi, xlo, T_SEQ * D_MODEL / 4);
    for (int i = 0; i < 4; i++)
        split_kernel<<<D_MODEL * D_MODEL / 1024, 256>>>(
            W[i], whi + (size_t)i * D_MODEL * D_MODEL, wlo + (size_t)i * D_MODEL * D_MODEL,
            D_MODEL * D_MODEL / 4);

    // 2) fused Q/K/V/G projections (weight slots 0..3)  [launch index 5]
    {
        dim3 grid(D_MODEL / 128, T_SEQ / 128, 4);
        mma_gemm_kernel<<<grid, 256, gm_smem>>>(xhi, xlo, bg, qb, kb, vb, gb, 0);
    }
    combine_qg_kernel<<<T_SEQ * D_MODEL / 256, 256>>>();

    // split Wo (needed only for the last GEMM)
    split_kernel<<<D_MODEL * D_MODEL / 1024, 256>>>(
        W[4], whi + (size_t)4 * D_MODEL * D_MODEL, wlo + (size_t)4 * D_MODEL * D_MODEL,
        D_MODEL * D_MODEL / 4);

    // 3) attention chunk pipeline (fp32)
    chunk_state_kernel<<<NH * NCHUNK, 256, cs_smem>>>();
    prefix_kernel<<<NH, 256>>>(out);
    chunk_out_kernel<<<NH * NCHUNK, 256, co_smem>>>();

    // 4) output projection (weight slot 4)
    split_kernel<<<T_SEQ * D_MODEL / 1024, 256>>>(ab, athi, atlo, T_SEQ * D_MODEL / 4);
    {
        dim3 grid(D_MODEL / 128, T_SEQ / 128, 1);
        mma_gemm_kernel<<<grid, 256, gm_smem>>>(athi, atlo, nullptr, out, out, out, out, 4);
    }
}

// round 6
// speedup vs baseline: 2.2724x; 1.1370x over previous
#include <cuda_runtime.h>
#include <cuda_bf16.h>
#include <math.h>
#include <stdint.h>

#define T_SEQ   2048
#define D_MODEL 1024
#define NH      16
#define DH      64
#define CHUNK   128
#define NCHUNK  (T_SEQ / CHUNK)   // 16
#define KT      32                // K elems per tile chunk (64B rows)
#define NKC     (D_MODEL / KT)    // 32 mainloop iterations
#define TILE_B  8192              // 128 rows * 64B
#define STAGE_B 32768             // Ahi, Alo, Whi, Wlo tiles
#define NST     3

// ---------------- scratch (static __device__ arrays; no allocation) ----------
__device__ __align__(256) float g_q  [T_SEQ * D_MODEL];
__device__ __align__(256) float g_g  [T_SEQ * D_MODEL];
__device__ __align__(256) float g_kf [T_SEQ * D_MODEL];
__device__ __align__(256) float g_v  [T_SEQ * D_MODEL];
__device__ __align__(256) float g_at [T_SEQ * D_MODEL];
__device__ __align__(256) float g_Sc  [NH * NCHUNK * DH * DH];
__device__ __align__(256) float g_Spre[NH * NCHUNK * DH * DH];
__device__ __align__(256) float g_zc  [NH * NCHUNK * DH];
__device__ __align__(256) float g_zpre[NH * NCHUNK * DH];
__device__ __align__(256) __nv_bfloat16 g_xhi [T_SEQ * D_MODEL];
__device__ __align__(256) __nv_bfloat16 g_xlo [T_SEQ * D_MODEL];
__device__ __align__(256) __nv_bfloat16 g_Whi [5 * D_MODEL * D_MODEL];
__device__ __align__(256) __nv_bfloat16 g_Wlo [5 * D_MODEL * D_MODEL];
__device__ __align__(256) __nv_bfloat16 g_athi[T_SEQ * D_MODEL];
__device__ __align__(256) __nv_bfloat16 g_atlo[T_SEQ * D_MODEL];

__device__ __forceinline__ float softplus_f(float x) {
    return (x > 20.f) ? x : log1pf(expf(x));
}

__device__ __forceinline__ void split4(float4 v, __nv_bfloat162* hi2, __nv_bfloat162* lo2) {
    __nv_bfloat16 h0 = __float2bfloat16_rn(v.x), h1 = __float2bfloat16_rn(v.y);
    __nv_bfloat16 h2 = __float2bfloat16_rn(v.z), h3 = __float2bfloat16_rn(v.w);
    hi2[0].x = h0; hi2[0].y = h1; hi2[1].x = h2; hi2[1].y = h3;
    lo2[0].x = __float2bfloat16_rn(v.x - __bfloat162float(h0));
    lo2[0].y = __float2bfloat16_rn(v.y - __bfloat162float(h1));
    lo2[1].x = __float2bfloat16_rn(v.z - __bfloat162float(h2));
    lo2[1].y = __float2bfloat16_rn(v.w - __bfloat162float(h3));
}

// =============== split kernels: fp32 -> (hi, lo) bf16 =======================
__global__ __launch_bounds__(256) void split_kernel(const float* __restrict__ src,
                                                    __nv_bfloat16* __restrict__ hi,
                                                    __nv_bfloat16* __restrict__ lo, int n4) {
    int i = blockIdx.x * 256 + threadIdx.x;
    if (i >= n4) return;
    __nv_bfloat162 H[2], L[2];
    split4(((const float4*)src)[i], H, L);
    ((__nv_bfloat162*)hi)[i * 2 + 0] = H[0];
    ((__nv_bfloat162*)hi)[i * 2 + 1] = H[1];
    ((__nv_bfloat162*)lo)[i * 2 + 0] = L[0];
    ((__nv_bfloat162*)lo)[i * 2 + 1] = L[1];
}

// batched: all 5 weight matrices in one launch (blockIdx.y selects)
__global__ __launch_bounds__(256) void split5_kernel(
    const float* __restrict__ s0, const float* __restrict__ s1,
    const float* __restrict__ s2, const float* __restrict__ s3,
    const float* __restrict__ s4)
{
    const float* srcs[5] = {s0, s1, s2, s3, s4};
    int z = blockIdx.y;
    int i = blockIdx.x * 256 + threadIdx.x;              // < 262144
    size_t off = (size_t)z * (D_MODEL * D_MODEL / 4);
    __nv_bfloat162 H[2], L[2];
    split4(((const float4*)srcs[z])[i], H, L);
    ((__nv_bfloat162*)g_Whi)[(off + i) * 2 + 0] = H[0];
    ((__nv_bfloat162*)g_Whi)[(off + i) * 2 + 1] = H[1];
    ((__nv_bfloat162*)g_Wlo)[(off + i) * 2 + 0] = L[0];
    ((__nv_bfloat162*)g_Wlo)[(off + i) * 2 + 1] = L[1];
}

// ======== fused 3-term split-bf16 GEMM: C = A * W^T + activation ============
// Block 128x128, 8 warps (2M x 4N), warp tile 64x32, KT=32 stages with SW64
// swizzle, 3-stage cp.async, all 3 precision terms per K-chunk.
__device__ __forceinline__ uint32_t sw64(int row, int j) {
    return (uint32_t)(row * 64 + 16 * (j ^ ((row >> 1) & 3)));
}

__global__ __launch_bounds__(256, 2) void mma_gemm_kernel(
    const __nv_bfloat16* __restrict__ Ahi, const __nv_bfloat16* __restrict__ Alo,
    const float* __restrict__ bias,
    float* C0, float* C1, float* C2, float* C3, int wbase)
{
    extern __shared__ __nv_bfloat16 sm[];
    const int tid = threadIdx.x, lane = tid & 31, wid = tid >> 5;
    const int g = lane >> 2, t = lane & 3;
    const int warpM = (wid & 1) * 64, warpN = (wid >> 1) * 32;
    const int z = blockIdx.z, widx = wbase + z;
    const int m0 = blockIdx.y * 128, n0 = blockIdx.x * 128;

    const __nv_bfloat16* Wh = g_Whi + (size_t)widx * D_MODEL * D_MODEL;
    const __nv_bfloat16* Wl = g_Wlo + (size_t)widx * D_MODEL * D_MODEL;
    float* Cs[4] = {C0, C1, C2, C3};
    float* C = Cs[z];
    const int mode = (widx <= 1) ? 1 : (widx == 3 ? 2 : 0);

    float acc[4][4][4];
    #pragma unroll
    for (int a = 0; a < 4; a++)
        #pragma unroll
        for (int b = 0; b < 4; b++)
            #pragma unroll
            for (int c = 0; c < 4; c++) acc[a][b][c] = 0.f;

    const uint32_t smb = (uint32_t)__cvta_generic_to_shared(sm);

    // ldmatrix lane roles
    const int arow = (lane & 7) + ((lane >> 3) & 1) * 8;  // A: row within 16-band
    const int ajl  = lane >> 4;                           // A: k-half
    const int bsel = lane >> 3;                           // B: matrix 0..3
    const int brow = (lane & 7) + ((bsel >> 1) & 1) * 8;  // B: row within 16-band
    const int bjl  = bsel & 1;                            // B: k-half

    auto issue = [&](int kc) {
        const uint32_t sbase = smb + (kc % NST) * STAGE_B;
        #pragma unroll
        for (int r = 0; r < 2; r++) {
            int id = tid + r * 256, row = id >> 2, c = id & 3;
            uint32_t off = sw64(row, c);
            size_t ga = (size_t)(m0 + row) * D_MODEL + kc * KT + c * 8;
            size_t gb = (size_t)(n0 + row) * D_MODEL + kc * KT + c * 8;
            asm volatile("cp.async.cg.shared.global [%0], [%1], 16;" :: "r"(sbase + off),              "l"((const void*)(Ahi + ga)));
            asm volatile("cp.async.cg.shared.global [%0], [%1], 16;" :: "r"(sbase + TILE_B + off),     "l"((const void*)(Alo + ga)));
            asm volatile("cp.async.cg.shared.global [%0], [%1], 16;" :: "r"(sbase + 2 * TILE_B + off), "l"((const void*)(Wh + gb)));
            asm volatile("cp.async.cg.shared.global [%0], [%1], 16;" :: "r"(sbase + 3 * TILE_B + off), "l"((const void*)(Wl + gb)));
        }
        asm volatile("cp.async.commit_group;" ::: "memory");
    };

    issue(0); issue(1); issue(2);

    for (int it = 0; it < NKC; it++) {
        if (it < NKC - 2)       asm volatile("cp.async.wait_group 2;" ::: "memory");
        else if (it == NKC - 2) asm volatile("cp.async.wait_group 1;" ::: "memory");
        else                    asm volatile("cp.async.wait_group 0;" ::: "memory");
        __syncthreads();

        const uint32_t sbase = smb + (it % NST) * STAGE_B;
        #pragma unroll
        for (int ks = 0; ks < 2; ks++) {
            uint32_t ahif[4][4], alof[4][4], bf[4][2];
            #pragma unroll
            for (int mt = 0; mt < 4; mt++) {
                uint32_t addr = sbase + sw64(warpM + mt * 16 + arow, ks * 2 + ajl);
                asm volatile("ldmatrix.sync.aligned.m8n8.x4.shared.b16 {%0,%1,%2,%3}, [%4];"
                             : "=r"(ahif[mt][0]), "=r"(ahif[mt][1]), "=r"(ahif[mt][2]), "=r"(ahif[mt][3])
                             : "r"(addr));
            }
            #pragma unroll
            for (int p = 0; p < 2; p++) {  // Whi fragments
                uint32_t addr = sbase + 2 * TILE_B + sw64(warpN + p * 16 + brow, ks * 2 + bjl);
                asm volatile("ldmatrix.sync.aligned.m8n8.x4.shared.b16 {%0,%1,%2,%3}, [%4];"
                             : "=r"(bf[2 * p][0]), "=r"(bf[2 * p][1]),
                               "=r"(bf[2 * p + 1][0]), "=r"(bf[2 * p + 1][1])
                             : "r"(addr));
            }
            #pragma unroll
            for (int mt = 0; mt < 4; mt++)   // Ahi * Whi
                #pragma unroll
                for (int nt = 0; nt < 4; nt++)
                    asm volatile(
                        "mma.sync.aligned.m16n8k16.row.col.f32.bf16.bf16.f32 "
                        "{%0,%1,%2,%3}, {%4,%5,%6,%7}, {%8,%9}, {%0,%1,%2,%3};"
                        : "+f"(acc[mt][nt][0]), "+f"(acc[mt][nt][1]),
                          "+f"(acc[mt][nt][2]), "+f"(acc[mt][nt][3])
                        : "r"(ahif[mt][0]), "r"(ahif[mt][1]), "r"(ahif[mt][2]), "r"(ahif[mt][3]),
                          "r"(bf[nt][0]), "r"(bf[nt][1]));
            #pragma unroll
            for (int mt = 0; mt < 4; mt++) {
                uint32_t addr = sbase + TILE_B + sw64(warpM + mt * 16 + arow, ks * 2 + ajl);
                asm volatile("ldmatrix.sync.aligned.m8n8.x4.shared.b16 {%0,%1,%2,%3}, [%4];"
                             : "=r"(alof[mt][0]), "=r"(alof[mt][1]), "=r"(alof[mt][2]), "=r"(alof[mt][3])
                             : "r"(addr));
            }
            #pragma unroll
            for (int mt = 0; mt < 4; mt++)   // Alo * Whi
                #pragma unroll
                for (int nt = 0; nt < 4; nt++)
                    asm volatile(
                        "mma.sync.aligned.m16n8k16.row.col.f32.bf16.bf16.f32 "
                        "{%0,%1,%2,%3}, {%4,%5,%6,%7}, {%8,%9}, {%0,%1,%2,%3};"
                        : "+f"(acc[mt][nt][0]), "+f"(acc[mt][nt][1]),
                          "+f"(acc[mt][nt][2]), "+f"(acc[mt][nt][3])
                        : "r"(alof[mt][0]), "r"(alof[mt][1]), "r"(alof[mt][2]), "r"(alof[mt][3]),
                          "r"(bf[nt][0]), "r"(bf[nt][1]));
            #pragma unroll
            for (int p = 0; p < 2; p++) {  // Wlo fragments (reuse bf)
                uint32_t addr = sbase + 3 * TILE_B + sw64(warpN + p * 16 + brow, ks * 2 + bjl);
                asm volatile("ldmatrix.sync.aligned.m8n8.x4.shared.b16 {%0,%1,%2,%3}, [%4];"
                             : "=r"(bf[2 * p][0]), "=r"(bf[2 * p][1]),
                               "=r"(bf[2 * p + 1][0]), "=r"(bf[2 * p + 1][1])
                             : "r"(addr));
            }
            #pragma unroll
            for (int mt = 0; mt < 4; mt++)   // Ahi * Wlo
                #pragma unroll
                for (int nt = 0; nt < 4; nt++)
                    asm volatile(
                        "mma.sync.aligned.m16n8k16.row.col.f32.bf16.bf16.f32 "
                        "{%0,%1,%2,%3}, {%4,%5,%6,%7}, {%8,%9}, {%0,%1,%2,%3};"
                        : "+f"(acc[mt][nt][0]), "+f"(acc[mt][nt][1]),
                          "+f"(acc[mt][nt][2]), "+f"(acc[mt][nt][3])
                        : "r"(ahif[mt][0]), "r"(ahif[mt][1]), "r"(ahif[mt][2]), "r"(ahif[mt][3]),
                          "r"(bf[nt][0]), "r"(bf[nt][1]));
        }
        __syncthreads();
        if (it + NST < NKC) issue(it + NST);
    }

    // ---------------- epilogue: activation + direct stores ------------------
    #pragma unroll
    for (int mt = 0; mt < 4; mt++) {
        int r0 = m0 + warpM + mt * 16 + g;
        #pragma unroll
        for (int nt = 0; nt < 4; nt++) {
            int c0 = n0 + warpN + nt * 8 + 2 * t;
            float v0 = acc[mt][nt][0], v1 = acc[mt][nt][1];
            float v2 = acc[mt][nt][2], v3 = acc[mt][nt][3];
            if (mode == 1) {
                v0 = softplus_f(v0); v1 = softplus_f(v1);
                v2 = softplus_f(v2); v3 = softplus_f(v3);
            } else if (mode == 2) {
                float b0 = __ldg(&bias[c0]), b1 = __ldg(&bias[c0 + 1]);
                v0 = 1.f / (1.f + expf(-(v0 + b0)));
                v1 = 1.f / (1.f + expf(-(v1 + b1)));
                v2 = 1.f / (1.f + expf(-(v2 + b0)));
                v3 = 1.f / (1.f + expf(-(v3 + b1)));
            }
            float2 p0; p0.x = v0; p0.y = v1;
            float2 p1; p1.x = v2; p1.y = v3;
            *(float2*)&C[(size_t)r0 * D_MODEL + c0]       = p0;
            *(float2*)&C[(size_t)(r0 + 8) * D_MODEL + c0] = p1;
        }
    }
}

// qf = softplus(q) * (sigmoid(gate) + 1e-6)
__global__ void combine_qg_kernel() {
    int i = blockIdx.x * 256 + threadIdx.x;
    g_q[i] = g_q[i] * (g_g[i] + 1e-6f);
}

// ------------- per-(head,chunk) local state S_c = Kf^T V, z_c = sum kf ------
__global__ __launch_bounds__(256) void chunk_state_kernel() {
    extern __shared__ float smf[];
    float* Kc = smf;
    float* Vc = smf + CHUNK * DH;
    const int head = blockIdx.x >> 4, chunk = blockIdx.x & 15;
    const int t0 = chunk * CHUNK, col0 = head * DH;
    const int tid = threadIdx.x;

    for (int i = tid; i < CHUNK * DH / 4; i += 256) {
        int tt = i >> 4, c4 = (i & 15) << 2;
        *(float4*)&Kc[tt * DH + c4] = *(const float4*)&g_kf[(size_t)(t0 + tt) * D_MODEL + col0 + c4];
        *(float4*)&Vc[tt * DH + c4] = *(const float4*)&g_v [(size_t)(t0 + tt) * D_MODEL + col0 + c4];
    }
    __syncthreads();

    const int d = tid >> 2, e0 = (tid & 3) << 4;
    float acc[16] = {};
    float z = 0.f;
    for (int tt = 0; tt < CHUNK; tt++) {
        float kv = Kc[tt * DH + d];
        z += kv;
        #pragma unroll
        for (int jj = 0; jj < 4; jj++) {
            float4 vv = *(float4*)&Vc[tt * DH + e0 + jj * 4];
            acc[jj * 4 + 0] = fmaf(kv, vv.x, acc[jj * 4 + 0]);
            acc[jj * 4 + 1] = fmaf(kv, vv.y, acc[jj * 4 + 1]);
            acc[jj * 4 + 2] = fmaf(kv, vv.z, acc[jj * 4 + 2]);
            acc[jj * 4 + 3] = fmaf(kv, vv.w, acc[jj * 4 + 3]);
        }
    }
    size_t base = (size_t)blockIdx.x * (DH * DH);
    #pragma unroll
    for (int j = 0; j < 16; j++) g_Sc[base + d * DH + e0 + j] = acc[j];
    if ((tid & 3) == 0) g_zc[blockIdx.x * DH + d] = z;
}

// ------------- sequential prefix over the 16 chunks (per head) --------------
__global__ __launch_bounds__(256) void prefix_kernel(float* __restrict__ out) {
    const int head = blockIdx.x, tid = threadIdx.x;
    float acc[16] = {};
    for (int c = 0; c < NCHUNK; c++) {
        size_t base = ((size_t)head * NCHUNK + c) * (DH * DH);
        #pragma unroll
        for (int k = 0; k < 16; k++) {
            g_Spre[base + tid + k * 256] = acc[k];
            acc[k] += g_Sc[base + tid + k * 256];
        }
    }
    float* kv_out = out + (size_t)T_SEQ * D_MODEL;
    #pragma unroll
    for (int k = 0; k < 16; k++)
        kv_out[(size_t)head * DH * DH + tid + k * 256] = acc[k];

    if (tid < DH) {
        float z = 0.f;
        for (int c = 0; c < NCHUNK; c++) {
            int base = (head * NCHUNK + c) * DH;
            g_zpre[base + tid] = z;
            z += g_zc[base + tid];
        }
        float* z_out = out + (size_t)T_SEQ * D_MODEL + NH * DH * DH;
        z_out[head * DH + tid] = z;
    }
}

// ------------- per-(head,chunk) output: causal intra + inter via S_prefix ---
#define QT_STRIDE 132
#define AS_STRIDE 132
#define CO_SMEM_FLOATS (DH*QT_STRIDE*2 + CHUNK*DH + DH*DH + CHUNK*AS_STRIDE + DH + CHUNK)

__global__ __launch_bounds__(256) void chunk_out_kernel() {
    extern __shared__ float smf[];
    float* Qt  = smf;
    float* Kt  = Qt + DH * QT_STRIDE;
    float* Vs  = Kt + DH * QT_STRIDE;
    float* Ss  = Vs + CHUNK * DH;
    float* As  = Ss + DH * DH;
    float* zs  = As + CHUNK * AS_STRIDE;
    float* den = zs + DH;
    const int head = blockIdx.x >> 4, chunk = blockIdx.x & 15;
    const int t0 = chunk * CHUNK, col0 = head * DH;
    const int tid = threadIdx.x;

    for (int i = tid; i < CHUNK * DH / 4; i += 256) {
        int tt = i >> 4, c4 = (i & 15) << 2;
        float4 q4 = *(const float4*)&g_q [(size_t)(t0 + tt) * D_MODEL + col0 + c4];
        Qt[(c4 + 0) * QT_STRIDE + tt] = q4.x; Qt[(c4 + 1) * QT_STRIDE + tt] = q4.y;
        Qt[(c4 + 2) * QT_STRIDE + tt] = q4.z; Qt[(c4 + 3) * QT_STRIDE + tt] = q4.w;
        float4 k4 = *(const float4*)&g_kf[(size_t)(t0 + tt) * D_MODEL + col0 + c4];
        Kt[(c4 + 0) * QT_STRIDE + tt] = k4.x; Kt[(c4 + 1) * QT_STRIDE + tt] = k4.y;
        Kt[(c4 + 2) * QT_STRIDE + tt] = k4.z; Kt[(c4 + 3) * QT_STRIDE + tt] = k4.w;
        *(float4*)&Vs[tt * DH + c4] = *(const float4*)&g_v[(size_t)(t0 + tt) * D_MODEL + col0 + c4];
    }
    {
        size_t base = ((size_t)head * NCHUNK + chunk) * (DH * DH);
        for (int i = tid; i < DH * DH / 4; i += 256)
            *(float4*)&Ss[i * 4] = *(const float4*)&g_Spre[base + i * 4];
    }
    if (tid < DH)    zs[tid]  = g_zpre[(head * NCHUNK + chunk) * DH + tid];
    if (tid < CHUNK) den[tid] = 0.f;
    __syncthreads();

    {
        const int tx = tid & 15, ty = tid >> 4;
        float a[8][8] = {};
        for (int k = 0; k < DH; k++) {
            float qr[8], kr[8];
            *(float4*)&qr[0] = *(float4*)&Qt[k * QT_STRIDE + ty * 8];
            *(float4*)&qr[4] = *(float4*)&Qt[k * QT_STRIDE + ty * 8 + 4];
            *(float4*)&kr[0] = *(float4*)&Kt[k * QT_STRIDE + tx * 8];
            *(float4*)&kr[4] = *(float4*)&Kt[k * QT_STRIDE + tx * 8 + 4];
            #pragma unroll
            for (int i = 0; i < 8; i++)
                #pragma unroll
                for (int j = 0; j < 8; j++)
                    a[i][j] = fmaf(qr[i], kr[j], a[i][j]);
        }
        #pragma unroll
        for (int i = 0; i < 8; i++) {
            int tr = ty * 8 + i;
            float rs = 0.f;
            #pragma unroll
            for (int j = 0; j < 8; j++) {
                int s = tx * 8 + j;
                float vv = (s <= tr) ? a[i][j] : 0.f;
                As[tr * AS_STRIDE + s] = vv;
                rs += vv;
            }
            atomicAdd(&den[tr], rs);
        }
    }
    __syncthreads();
    if (tid < CHUNK) {
        float dz = 0.f;
        #pragma unroll 8
        for (int d = 0; d < DH; d++) dz += Qt[d * QT_STRIDE + tid] * zs[d];
        den[tid] += dz + 1e-6f;
    }
    __syncthreads();

    {
        const int tr = tid & 127;
        const int e0 = (tid >> 7) * 32;
        float acc[32] = {};
        for (int d = 0; d < DH; d++) {
            float qv = Qt[d * QT_STRIDE + tr];
            #pragma unroll
            for (int jj = 0; jj < 8; jj++) {
                float4 sv = *(float4*)&Ss[d * DH + e0 + jj * 4];
                acc[jj * 4 + 0] = fmaf(qv, sv.x, acc[jj * 4 + 0]);
                acc[jj * 4 + 1] = fmaf(qv, sv.y, acc[jj * 4 + 1]);
                acc[jj * 4 + 2] = fmaf(qv, sv.z, acc[jj * 4 + 2]);
                acc[jj * 4 + 3] = fmaf(qv, sv.w, acc[jj * 4 + 3]);
            }
        }
        for (int s = 0; s < CHUNK; s++) {
            float av = As[tr * AS_STRIDE + s];
            #pragma unroll
            for (int jj = 0; jj < 8; jj++) {
                float4 vv = *(float4*)&Vs[s * DH + e0 + jj * 4];
                acc[jj * 4 + 0] = fmaf(av, vv.x, acc[jj * 4 + 0]);
                acc[jj * 4 + 1] = fmaf(av, vv.y, acc[jj * 4 + 1]);
                acc[jj * 4 + 2] = fmaf(av, vv.z, acc[jj * 4 + 2]);
                acc[jj * 4 + 3] = fmaf(av, vv.w, acc[jj * 4 + 3]);
            }
        }
        float dinv = 1.f / den[tr];
        #pragma unroll
        for (int jj = 0; jj < 8; jj++) {
            float4 o;
            o.x = acc[jj * 4 + 0] * dinv; o.y = acc[jj * 4 + 1] * dinv;
            o.z = acc[jj * 4 + 2] * dinv; o.w = acc[jj * 4 + 3] * dinv;
            *(float4*)&g_at[(size_t)(t0 + tr) * D_MODEL + col0 + e0 + jj * 4] = o;
        }
    }
}

// ---------------------------------------------------------------------------
extern "C" void kernel_launch(void* const* d_in, const int* in_sizes, int n_in,
                              void* d_out, int out_size)
{
    const float* x  = (const float*)d_in[0];
    // weight slots: 0=Wq 1=Wk 2=Wv 3=Wg 4=Wo
    const float* Wq = (const float*)d_in[1];
    const float* Wk = (const float*)d_in[2];
    const float* Wv = (const float*)d_in[3];
    const float* Wo = (const float*)d_in[4];
    const float* Wg = (const float*)d_in[5];
    const float* bg = (const float*)d_in[6];
    float* out = (float*)d_out;

    float *qb, *gb, *kb, *vb, *ab;
    cudaGetSymbolAddress((void**)&qb, g_q);
    cudaGetSymbolAddress((void**)&gb, g_g);
    cudaGetSymbolAddress((void**)&kb, g_kf);
    cudaGetSymbolAddress((void**)&vb, g_v);
    cudaGetSymbolAddress((void**)&ab, g_at);
    __nv_bfloat16 *xhi, *xlo, *athi, *atlo;
    cudaGetSymbolAddress((void**)&xhi, g_xhi);
    cudaGetSymbolAddress((void**)&xlo, g_xlo);
    cudaGetSymbolAddress((void**)&athi, g_athi);
    cudaGetSymbolAddress((void**)&atlo, g_atlo);

    const int cs_smem = CHUNK * DH * 2 * sizeof(float);
    const int co_smem = CO_SMEM_FLOATS * sizeof(float);
    const int gm_smem = NST * STAGE_B;   // 98304 B
    cudaFuncSetAttribute(chunk_state_kernel, cudaFuncAttributeMaxDynamicSharedMemorySize, cs_smem);
    cudaFuncSetAttribute(chunk_out_kernel,   cudaFuncAttributeMaxDynamicSharedMemorySize, co_smem);
    cudaFuncSetAttribute(mma_gemm_kernel,    cudaFuncAttributeMaxDynamicSharedMemorySize, gm_smem);

    // 1) splits: x (1 launch) + all 5 weights (1 batched launch)
    split_kernel<<<T_SEQ * D_MODEL / 1024, 256>>>(x, xhi, xlo, T_SEQ * D_MODEL / 4);
    {
        dim3 grid(D_MODEL * D_MODEL / 1024, 5);
        split5_kernel<<<grid, 256>>>(Wq, Wk, Wv, Wg, Wo);
    }

    // 2) fused Q/K/V/G projections (weight slots 0..3)
    {
        dim3 grid(D_MODEL / 128, T_SEQ / 128, 4);
        mma_gemm_kernel<<<grid, 256, gm_smem>>>(xhi, xlo, bg, qb, kb, vb, gb, 0);
    }
    combine_qg_kernel<<<T_SEQ * D_MODEL / 256, 256>>>();

    // 3) attention chunk pipeline (fp32)
    chunk_state_kernel<<<NH * NCHUNK, 256, cs_smem>>>();
    prefix_kernel<<<NH, 256>>>(out);
    chunk_out_kernel<<<NH * NCHUNK, 256, co_smem>>>();

    // 4) output projection (weight slot 4)
    split_kernel<<<T_SEQ * D_MODEL / 1024, 256>>>(ab, athi, atlo, T_SEQ * D_MODEL / 4);
    {
        dim3 grid(D_MODEL / 128, T_SEQ / 128, 1);
        mma_gemm_kernel<<<grid, 256, gm_smem>>>(athi, atlo, nullptr, out, out, out, out, 4);
    }
}